// round 2
// baseline (speedup 1.0000x reference)
#include <cuda_runtime.h>
#include <math.h>
#include <stdint.h>

#define BB 16
#define CC 32
#define NN 512
#define T1 192
#define T2 96
#define L1 97
#define L2 49
#define EE 64

static constexpr size_t SZ1 = (size_t)BB*CC*NN*T1;   // 50,331,648
static constexpr size_t SZ2 = (size_t)BB*CC*NN*T2;   // 25,165,824

// ---------------- scratch (static device globals; no allocation) ----------------
__device__ float g_bufA[SZ1];
__device__ float g_bufB[SZ1];
__device__ float g_bufC[SZ1];
__device__ float g_bufD[SZ2];
__device__ float g_bufE[SZ2];
__device__ float g_bufF[SZ2];
__device__ float g_Mc[CC*T1*T1];
__device__ float g_Mt[CC*T1*T1];
__device__ float g_C1[CC*T1*T1];
__device__ float g_C2[CC*T2*T2];
__device__ float g_cos1[L1*T1];
__device__ float g_sin1[L1*T1];
__device__ float g_cos2[L2*T2];
__device__ float g_sin2[L2*T2];
__device__ float g_K1[CC*T1];
__device__ float g_K2[CC*T2];
__device__ float g_feat[BB*CC*T1];
__device__ float g_gate[BB*T1];

__device__ __forceinline__ float gelu_t(float x) {
    float x3 = x*x*x;
    return 0.5f*x*(1.0f + tanhf(0.7978845608028654f*(x + 0.044715f*x3)));
}

// ---------------- precompute: cos/sin tables ----------------
__global__ void k_tables() {
    int i = blockIdx.x*blockDim.x + threadIdx.x;
    if (i < L1*T1) {
        int h = i / T1, t = i % T1;
        int m = (h*t) % T1;
        float a = (float)m * (1.0f/96.0f);   // 2*h*t/T1 in units of pi
        g_cos1[i] = cospif(a);
        g_sin1[i] = sinpif(a);
    }
    int j = i - L1*T1;
    if (j >= 0 && j < L2*T2) {
        int h = j / T2, t = j % T2;
        int m = (h*t) % T2;
        float a = (float)m * (1.0f/48.0f);
        g_cos2[j] = cospif(a);
        g_sin2[j] = sinpif(a);
    }
}

// Mc[l][t][t'] = sum_h (w_h/T1) Lc[l,h] cos(ht)cos(ht');  Mt with Lt, sin*sin
__global__ void k_buildM(const float* __restrict__ Lc, const float* __restrict__ Lt) {
    int t = blockIdx.x, l = blockIdx.y, tp = threadIdx.x;
    float ac = 0.f, as = 0.f;
    for (int h = 0; h < L1; h++) {
        float w = (h == 0 || h == L1-1) ? (1.0f/T1) : (2.0f/T1);
        float lc = Lc[l*L1+h]*w, lt = Lt[l*L1+h]*w;
        ac = fmaf(lc * g_cos1[h*T1+t], g_cos1[h*T1+tp], ac);
        as = fmaf(lt * g_sin1[h*T1+t], g_sin1[h*T1+tp], as);
    }
    size_t o = ((size_t)l*T1 + t)*T1 + tp;
    g_Mc[o] = ac;
    g_Mt[o] = as;
}

__global__ void k_buildK1(const float* __restrict__ Wr, const float* __restrict__ Wi) {
    int i = blockIdx.x*blockDim.x + threadIdx.x;
    if (i >= CC*T1) return;
    int c = i / T1, d = i % T1;
    float acc = 0.f;
    for (int h = 0; h < L1; h++) {
        float w = (h == 0 || h == L1-1) ? (1.0f/T1) : (2.0f/T1);
        acc += w * (Wr[c*L1+h]*g_cos1[h*T1+d] - Wi[c*L1+h]*g_sin1[h*T1+d]);
    }
    g_K1[i] = acc;
}
__global__ void k_expand1() {
    size_t i = (size_t)blockIdx.x*blockDim.x + threadIdx.x;
    if (i >= (size_t)CC*T1*T1) return;
    int s = (int)(i % T1);
    int t = (int)((i / T1) % T1);
    int c = (int)(i / ((size_t)T1*T1));
    g_C1[i] = g_K1[c*T1 + ((s - t + T1) % T1)];
}
__global__ void k_buildK2(const float* __restrict__ Wr, const float* __restrict__ Wi) {
    int i = blockIdx.x*blockDim.x + threadIdx.x;
    if (i >= CC*T2) return;
    int c = i / T2, d = i % T2;
    float acc = 0.f;
    for (int h = 0; h < L2; h++) {
        float w = (h == 0 || h == L2-1) ? (1.0f/T2) : (2.0f/T2);
        acc += w * (Wr[c*L2+h]*g_cos2[h*T2+d] - Wi[c*L2+h]*g_sin2[h*T2+d]);
    }
    g_K2[i] = acc;
}
__global__ void k_expand2() {
    size_t i = (size_t)blockIdx.x*blockDim.x + threadIdx.x;
    if (i >= (size_t)CC*T2*T2) return;
    int s = (int)(i % T2);
    int t = (int)((i / T2) % T2);
    int c = (int)(i / ((size_t)T2*T2));
    g_C2[i] = g_K2[c*T2 + ((s - t + T2) % T2)];
}

// ---------------- channel mix: u = Gc^T x, v = Gt^T x ----------------
__global__ void __launch_bounds__(256) k_chmix(const float* __restrict__ x,
                                               const float* __restrict__ Gc,
                                               const float* __restrict__ Gt) {
    __shared__ float sGc[CC*CC];
    __shared__ float sGt[CC*CC];
    int tid = threadIdx.x;
    for (int i = tid; i < CC*CC; i += 256) { sGc[i] = Gc[i]; sGt[i] = Gt[i]; }
    __syncthreads();
    int b = blockIdx.y;
    size_t m = (size_t)blockIdx.x*256 + tid;              // < NN*T1
    float au[CC], av[CC];
#pragma unroll
    for (int l = 0; l < CC; l++) { au[l] = 0.f; av[l] = 0.f; }
    for (int c = 0; c < CC; c++) {
        float xv = x[((size_t)(b*CC + c)*NN)*T1 + m];
#pragma unroll
        for (int l = 0; l < CC; l += 4) {
            float4 gc = *(const float4*)&sGc[c*CC + l];
            float4 gt = *(const float4*)&sGt[c*CC + l];
            au[l+0] = fmaf(xv, gc.x, au[l+0]); av[l+0] = fmaf(xv, gt.x, av[l+0]);
            au[l+1] = fmaf(xv, gc.y, au[l+1]); av[l+1] = fmaf(xv, gt.y, av[l+1]);
            au[l+2] = fmaf(xv, gc.z, au[l+2]); av[l+2] = fmaf(xv, gt.z, av[l+2]);
            au[l+3] = fmaf(xv, gc.w, au[l+3]); av[l+3] = fmaf(xv, gt.w, av[l+3]);
        }
    }
#pragma unroll
    for (int l = 0; l < CC; l++) {
        g_bufA[((size_t)(b*CC + l)*NN)*T1 + m] = au[l];
        g_bufB[((size_t)(b*CC + l)*NN)*T1 + m] = av[l];
    }
}

// ---------------- generic time matmul: Y = (X1 [+X2]) @ W [+ bias] ----------------
template<int TD, int SD, int TM, bool PERCH, bool ADD2, bool BIAS>
__global__ void __launch_bounds__(256) k_mm(const float* __restrict__ X1,
                                            const float* __restrict__ X2,
                                            const float* __restrict__ W,
                                            const float* __restrict__ bias,
                                            float* __restrict__ Y) {
    constexpr int KC = 16, JC = SD/16, RI = TM/16;
    __shared__ float xs[TM][KC+1];
    __shared__ float ws[KC][SD];
    int tid = threadIdx.x, tx = tid & 15, ty = tid >> 4;
    int c = blockIdx.y, b = blockIdx.z;
    size_t row0 = (size_t)(b*CC + c)*NN + (size_t)blockIdx.x*TM;
    const float* Wb = PERCH ? (W + (size_t)c*TD*SD) : W;
    float acc[RI][JC];
#pragma unroll
    for (int i = 0; i < RI; i++)
#pragma unroll
        for (int j = 0; j < JC; j++) acc[i][j] = 0.f;

    for (int kt = 0; kt < TD/KC; kt++) {
#pragma unroll
        for (int idx = tid; idx < TM*KC; idx += 256) {
            int rr = idx >> 4, kk = idx & 15;
            size_t gi = (row0 + rr)*TD + kt*KC + kk;
            float v = X1[gi];
            if (ADD2) v += X2[gi];
            xs[rr][kk] = v;
        }
#pragma unroll
        for (int idx = tid; idx < KC*SD; idx += 256) {
            int kk = idx / SD, ss = idx % SD;
            ws[kk][ss] = Wb[(size_t)(kt*KC + kk)*SD + ss];
        }
        __syncthreads();
#pragma unroll
        for (int k = 0; k < KC; k++) {
            float xv[RI], wv[JC];
#pragma unroll
            for (int i = 0; i < RI; i++) xv[i] = xs[ty + 16*i][k];
#pragma unroll
            for (int j = 0; j < JC; j++) wv[j] = ws[k][tx + 16*j];
#pragma unroll
            for (int i = 0; i < RI; i++)
#pragma unroll
                for (int j = 0; j < JC; j++) acc[i][j] = fmaf(xv[i], wv[j], acc[i][j]);
        }
        __syncthreads();
    }
#pragma unroll
    for (int i = 0; i < RI; i++)
#pragma unroll
        for (int j = 0; j < JC; j++) {
            int s = tx + 16*j;
            float o = acc[i][j];
            if (BIAS) o += bias[s];
            Y[(row0 + ty + 16*i)*SD + s] = o;
        }
}

// ---------------- freqmix: Y = resid + X1 @ Wa[c] + X2 @ Wb[c] ----------------
__global__ void __launch_bounds__(256) k_mm2(const float* __restrict__ X1,
                                             const float* __restrict__ X2,
                                             const float* __restrict__ Wa,
                                             const float* __restrict__ Wb,
                                             const float* __restrict__ resid,
                                             float* __restrict__ Y) {
    constexpr int TD = T1, SD = T1, TM = 64, KC = 16, JC = SD/16, RI = TM/16;
    __shared__ float xs1[TM][KC+1];
    __shared__ float xs2[TM][KC+1];
    __shared__ float wsa[KC][SD];
    __shared__ float wsb[KC][SD];
    int tid = threadIdx.x, tx = tid & 15, ty = tid >> 4;
    int c = blockIdx.y, b = blockIdx.z;
    size_t row0 = (size_t)(b*CC + c)*NN + (size_t)blockIdx.x*TM;
    const float* WaB = Wa + (size_t)c*TD*SD;
    const float* WbB = Wb + (size_t)c*TD*SD;
    float acc[RI][JC];
#pragma unroll
    for (int i = 0; i < RI; i++)
#pragma unroll
        for (int j = 0; j < JC; j++) acc[i][j] = 0.f;

    for (int kt = 0; kt < TD/KC; kt++) {
#pragma unroll
        for (int idx = tid; idx < TM*KC; idx += 256) {
            int rr = idx >> 4, kk = idx & 15;
            size_t gi = (row0 + rr)*TD + kt*KC + kk;
            xs1[rr][kk] = X1[gi];
            xs2[rr][kk] = X2[gi];
        }
#pragma unroll
        for (int idx = tid; idx < KC*SD; idx += 256) {
            int kk = idx / SD, ss = idx % SD;
            wsa[kk][ss] = WaB[(size_t)(kt*KC + kk)*SD + ss];
            wsb[kk][ss] = WbB[(size_t)(kt*KC + kk)*SD + ss];
        }
        __syncthreads();
#pragma unroll
        for (int k = 0; k < KC; k++) {
            float x1v[RI], x2v[RI], wav[JC], wbv[JC];
#pragma unroll
            for (int i = 0; i < RI; i++) { x1v[i] = xs1[ty+16*i][k]; x2v[i] = xs2[ty+16*i][k]; }
#pragma unroll
            for (int j = 0; j < JC; j++) { wav[j] = wsa[k][tx+16*j]; wbv[j] = wsb[k][tx+16*j]; }
#pragma unroll
            for (int i = 0; i < RI; i++)
#pragma unroll
                for (int j = 0; j < JC; j++) {
                    acc[i][j] = fmaf(x1v[i], wav[j], acc[i][j]);
                    acc[i][j] = fmaf(x2v[i], wbv[j], acc[i][j]);
                }
        }
        __syncthreads();
    }
#pragma unroll
    for (int i = 0; i < RI; i++)
#pragma unroll
        for (int j = 0; j < JC; j++) {
            int s = tx + 16*j;
            size_t gi = (row0 + ty + 16*i)*SD + s;
            Y[gi] = resid[gi] + acc[i][j];
        }
}

// ---------------- gmlp: Y = (X@W1) * gelu(X@W2), shared weights ----------------
template<int TD, int SD, int TM>
__global__ void __launch_bounds__(256) k_gmlp(const float* __restrict__ X,
                                              const float* __restrict__ W1,
                                              const float* __restrict__ W2,
                                              float* __restrict__ Y) {
    constexpr int KC = 16, JC = SD/16, RI = TM/16;
    __shared__ float xs[TM][KC+1];
    __shared__ float ws1[KC][SD];
    __shared__ float ws2[KC][SD];
    int tid = threadIdx.x, tx = tid & 15, ty = tid >> 4;
    int c = blockIdx.y, b = blockIdx.z;
    size_t row0 = (size_t)(b*CC + c)*NN + (size_t)blockIdx.x*TM;
    float a1[RI][JC], a2[RI][JC];
#pragma unroll
    for (int i = 0; i < RI; i++)
#pragma unroll
        for (int j = 0; j < JC; j++) { a1[i][j] = 0.f; a2[i][j] = 0.f; }

    for (int kt = 0; kt < TD/KC; kt++) {
#pragma unroll
        for (int idx = tid; idx < TM*KC; idx += 256) {
            int rr = idx >> 4, kk = idx & 15;
            xs[rr][kk] = X[(row0 + rr)*TD + kt*KC + kk];
        }
#pragma unroll
        for (int idx = tid; idx < KC*SD; idx += 256) {
            int kk = idx / SD, ss = idx % SD;
            ws1[kk][ss] = W1[(size_t)(kt*KC + kk)*SD + ss];
            ws2[kk][ss] = W2[(size_t)(kt*KC + kk)*SD + ss];
        }
        __syncthreads();
#pragma unroll
        for (int k = 0; k < KC; k++) {
            float xv[RI], w1v[JC], w2v[JC];
#pragma unroll
            for (int i = 0; i < RI; i++) xv[i] = xs[ty + 16*i][k];
#pragma unroll
            for (int j = 0; j < JC; j++) { w1v[j] = ws1[k][tx+16*j]; w2v[j] = ws2[k][tx+16*j]; }
#pragma unroll
            for (int i = 0; i < RI; i++)
#pragma unroll
                for (int j = 0; j < JC; j++) {
                    a1[i][j] = fmaf(xv[i], w1v[j], a1[i][j]);
                    a2[i][j] = fmaf(xv[i], w2v[j], a2[i][j]);
                }
        }
        __syncthreads();
    }
#pragma unroll
    for (int i = 0; i < RI; i++)
#pragma unroll
        for (int j = 0; j < JC; j++) {
            int s = tx + 16*j;
            Y[(row0 + ty + 16*i)*SD + s] = a1[i][j] * gelu_t(a2[i][j]);
        }
}

// ---------------- mean over n ----------------
template<int T>
__global__ void __launch_bounds__(T) k_meanN(const float* __restrict__ X) {
    int c = blockIdx.x, b = blockIdx.y, t = threadIdx.x;
    const float* p = X + ((size_t)(b*CC + c)*NN)*T + t;
    float s = 0.f;
    for (int n = 0; n < NN; n++) s += p[(size_t)n*T];
    g_feat[(b*CC + c)*T + t] = s * (1.0f/NN);
}

// ---------------- attn gate: g[b,t] = gelu(diag softmax(qk^T/8)) ----------------
template<int T>
__global__ void __launch_bounds__(T) k_gate(const float* __restrict__ Wq,
                                            const float* __restrict__ Wk) {
    __shared__ float ks[T][EE];
    int b = blockIdx.x, t = threadIdx.x;
    float q[EE], kk[EE];
#pragma unroll
    for (int e = 0; e < EE; e++) { q[e] = 0.f; kk[e] = 0.f; }
    for (int c = 0; c < CC; c++) {
        float f = g_feat[(b*CC + c)*T + t];
#pragma unroll
        for (int e = 0; e < EE; e++) {
            q[e]  = fmaf(f, Wq[c*EE + e], q[e]);
            kk[e] = fmaf(f, Wk[c*EE + e], kk[e]);
        }
    }
#pragma unroll
    for (int e = 0; e < EE; e++) ks[t][e] = kk[e];
    __syncthreads();
    float smax = -1e30f, stt = 0.f;
    for (int j = 0; j < T; j++) {
        float d = 0.f;
#pragma unroll
        for (int e = 0; e < EE; e++) d = fmaf(q[e], ks[j][e], d);
        d *= 0.125f;
        if (j == t) stt = d;
        smax = fmaxf(smax, d);
    }
    float ssum = 0.f;
    for (int j = 0; j < T; j++) {
        float d = 0.f;
#pragma unroll
        for (int e = 0; e < EE; e++) d = fmaf(q[e], ks[j][e], d);
        ssum += expf(d*0.125f - smax);
    }
    float p = expf(stt - smax) / ssum;
    g_gate[b*T + t] = gelu_t(p);
}

// ---------------- scale: Y = X * (1 + g[b,t]) ----------------
template<int T>
__global__ void __launch_bounds__(256) k_scale(const float* __restrict__ X,
                                               float* __restrict__ Y) {
    int b = blockIdx.y;
    size_t i = (size_t)blockIdx.x*256 + threadIdx.x;   // within batch b
    int t = (int)(i % T);
    float s = 1.0f + g_gate[b*T + t];
    size_t gi = (size_t)b*CC*NN*T + i;
    Y[gi] = X[gi] * s;
}

// ---------------- driver ----------------
extern "C" void kernel_launch(void* const* d_in, const int* in_sizes, int n_in,
                              void* d_out, int out_size) {
    const float* x   = (const float*)d_in[0];
    const float* Gc  = (const float*)d_in[3];
    const float* Lc  = (const float*)d_in[4];
    const float* Gt  = (const float*)d_in[5];
    const float* Lt  = (const float*)d_in[6];
    const float* f1r = (const float*)d_in[7];
    const float* f1i = (const float*)d_in[8];
    const float* f2r = (const float*)d_in[9];
    const float* f2i = (const float*)d_in[10];
    const float* Wfc = (const float*)d_in[11];
    const float* bfc = (const float*)d_in[12];
    const float* mi1 = (const float*)d_in[13];
    const float* mi2 = (const float*)d_in[14];
    const float* mo1 = (const float*)d_in[15];
    const float* mo2 = (const float*)d_in[16];
    const float* aiq = (const float*)d_in[17];
    const float* aik = (const float*)d_in[18];
    const float* aoq = (const float*)d_in[19];
    const float* aok = (const float*)d_in[20];
    float* out = (float*)d_out;

    float *bufA, *bufB, *bufC, *bufD, *bufE, *bufF, *Mc, *Mt, *C1, *C2;
    cudaGetSymbolAddress((void**)&bufA, g_bufA);
    cudaGetSymbolAddress((void**)&bufB, g_bufB);
    cudaGetSymbolAddress((void**)&bufC, g_bufC);
    cudaGetSymbolAddress((void**)&bufD, g_bufD);
    cudaGetSymbolAddress((void**)&bufE, g_bufE);
    cudaGetSymbolAddress((void**)&bufF, g_bufF);
    cudaGetSymbolAddress((void**)&Mc,   g_Mc);
    cudaGetSymbolAddress((void**)&Mt,   g_Mt);
    cudaGetSymbolAddress((void**)&C1,   g_C1);
    cudaGetSymbolAddress((void**)&C2,   g_C2);

    // precompute operator matrices
    k_tables<<<(L1*T1 + L2*T2 + 255)/256, 256>>>();
    k_buildM<<<dim3(T1, CC), T1>>>(Lc, Lt);
    k_buildK1<<<(CC*T1 + 255)/256, 256>>>(f1r, f1i);
    k_expand1<<<(int)(((size_t)CC*T1*T1 + 255)/256), 256>>>();
    k_buildK2<<<(CC*T2 + 255)/256, 256>>>(f2r, f2i);
    k_expand2<<<(int)(((size_t)CC*T2*T2 + 255)/256), 256>>>();

    // freq_attn_in: u = Gc^T x, v = Gt^T x ; xc = x + Mc[l] u + Mt[l] v
    k_chmix<<<dim3(NN*T1/256, BB), 256>>>(x, Gc, Gt);
    k_mm2<<<dim3(NN/64, CC, BB), 256>>>(bufA, bufB, Mc, Mt, x, bufC);

    // input-side layers
    for (int i = 0; i < 2; i++) {
        k_gmlp<T1, T1, 32><<<dim3(NN/32, CC, BB), 256>>>(bufC, mi1 + (size_t)i*T1*T1, mi2 + (size_t)i*T1*T1, bufA);
        k_meanN<T1><<<dim3(CC, BB), T1>>>(bufA);
        k_gate<T1><<<BB, T1>>>(aiq + i*CC*EE, aik + i*CC*EE);
        k_scale<T1><<<dim3(CC*NN*T1/256, BB), 256>>>(bufA, bufC);
    }

    // h_x = Circ1[c] (x + xc) ; h_y = h_x @ Wfc + b
    k_mm<T1, T1, 64, true,  true,  false><<<dim3(NN/64, CC, BB), 256>>>(x, bufC, C1, nullptr, bufA);
    k_mm<T1, T2, 64, false, false, true ><<<dim3(NN/64, CC, BB), 256>>>(bufA, nullptr, Wfc, bfc, bufD);

    // output-side layers
    const float* cur = bufD;
    for (int i = 0; i < 2; i++) {
        k_gmlp<T2, T2, 64><<<dim3(NN/64, CC, BB), 256>>>(cur, mo1 + (size_t)i*T2*T2, mo2 + (size_t)i*T2*T2, bufE);
        k_meanN<T2><<<dim3(CC, BB), T2>>>(bufE);
        k_gate<T2><<<BB, T2>>>(aoq + i*CC*EE, aok + i*CC*EE);
        k_scale<T2><<<dim3(CC*NN*T2/256, BB), 256>>>(bufE, bufF);
        cur = bufF;
    }

    // out = Circ2[c] (h_y + y_c)
    k_mm<T2, T2, 64, true, true, false><<<dim3(NN/64, CC, BB), 256>>>(bufD, bufF, C2, nullptr, out);
}